// round 1
// baseline (speedup 1.0000x reference)
#include <cuda_runtime.h>
#include <cuda_bf16.h>

// Problem constants
#define BB 2
#define CIN 256
#define HH 96
#define WW 96
#define COUT 256
#define KK2 9
#define HW (HH*WW)                 // 9216
#define MTOT (BB*HW)               // 18432
#define KKTOT (KK2*CIN)            // 2304
#define NGRP 32
#define GCH (COUT/NGRP)            // 8
#define GELEMS (GCH*HW)            // 73728

// Scratch (static device memory; allocation-free kernel_launch)
__device__ __align__(128) float g_off[BB*18*HW];        // offsets  [B,18,H,W]
__device__ __align__(128) float g_A[KKTOT*MTOT];        // im2col A^T: [KK, M], 170MB
__device__ __align__(128) float g_Wt[KKTOT*COUT];       // repacked weights [KK, Cout]
__device__ __align__(128) float g_O[MTOT*COUT];         // GEMM out (NHWC): [M, Cout]
__device__ __align__(128) float g_stats[NGRP*BB*2];     // per (b,g): sum, sumsq

// ---------------------------------------------------------------- zero stats
__global__ void zero_stats_kernel() {
    int i = threadIdx.x;
    if (i < NGRP*BB*2) g_stats[i] = 0.f;
}

// ---------------------------------------------------------------- offset conv
// off[b,j,h,w] = bias[j] + sum_{c,ky,kx} x[b,c,h-1+ky,w-1+kx] * ow[j,c,ky,kx]
// Tile 32x4 pixels, 128 threads, 18 accumulators/thread, loop over c with smem.
__global__ void offset_conv_kernel(const float* __restrict__ x,
                                   const float* __restrict__ ow,
                                   const float* __restrict__ ob) {
    __shared__ float xs[6][34];
    __shared__ float ws[18][9];
    const int w0 = blockIdx.x * 32;
    const int h0 = blockIdx.y * 4;
    const int b  = blockIdx.z;
    const int tx = threadIdx.x, ty = threadIdx.y;
    const int tid = ty * 32 + tx;               // 0..127

    float acc[18];
#pragma unroll
    for (int j = 0; j < 18; j++) acc[j] = 0.f;

    const float* xb = x + b * (CIN*HW);

    for (int c = 0; c < CIN; c++) {
        // load x tile 6x34 (with halo, zero-padded)
        for (int i = tid; i < 6*34; i += 128) {
            int r = i / 34, cc = i % 34;
            int y = h0 - 1 + r, xx = w0 - 1 + cc;
            float v = 0.f;
            if (y >= 0 && y < HH && xx >= 0 && xx < WW) v = xb[c*HW + y*WW + xx];
            xs[r][cc] = v;
        }
        // load 18x9 weights for this c
        for (int i = tid; i < 162; i += 128)
            ws[i/9][i%9] = ow[(i/9)*(CIN*9) + c*9 + (i%9)];
        __syncthreads();

        float xv[9];
#pragma unroll
        for (int t = 0; t < 9; t++) xv[t] = xs[ty + t/3][tx + t%3];
#pragma unroll
        for (int j = 0; j < 18; j++) {
            float a = acc[j];
#pragma unroll
            for (int t = 0; t < 9; t++) a += xv[t] * ws[j][t];
            acc[j] = a;
        }
        __syncthreads();
    }
    const int h = h0 + ty, w = w0 + tx;
#pragma unroll
    for (int j = 0; j < 18; j++)
        g_off[((b*18 + j)*HH + h)*WW + w] = acc[j] + ob[j];
}

// ---------------------------------------------------------------- gather/im2col
// One block = (b, k, h) row; 96 threads along w; loop over c.
// Writes A^T[kk = k*CIN+c][m = b*HW + h*W + w]  (m-contiguous => coalesced)
__global__ void gather_kernel(const float* __restrict__ x) {
    const int w = threadIdx.x;        // 0..95
    const int h = blockIdx.x;         // 0..95
    const int k = blockIdx.y;         // 0..8
    const int b = blockIdx.z;         // 0..1

    const int off_base = ((b*18 + 2*k)*HH + h)*WW + w;
    const float dy = g_off[off_base];
    const float dx = g_off[off_base + HW];

    const float sy = (float)(h - 1 + k/3) + dy;
    const float sx = (float)(w - 1 + k%3) + dx;
    const float y0f = floorf(sy), x0f = floorf(sx);
    const float fy = sy - y0f, fx = sx - x0f;
    const int y0 = (int)y0f, x0 = (int)x0f;
    const int y1 = y0 + 1,  x1 = x0 + 1;

    const bool vy0 = (y0 >= 0) && (y0 < HH), vy1 = (y1 >= 0) && (y1 < HH);
    const bool vx0 = (x0 >= 0) && (x0 < WW), vx1 = (x1 >= 0) && (x1 < WW);
    const float w00 = (vy0 && vx0) ? (1.f-fy)*(1.f-fx) : 0.f;
    const float w01 = (vy0 && vx1) ? (1.f-fy)*fx       : 0.f;
    const float w10 = (vy1 && vx0) ? fy*(1.f-fx)       : 0.f;
    const float w11 = (vy1 && vx1) ? fy*fx             : 0.f;

    const int cy0 = min(max(y0,0),HH-1), cy1 = min(max(y1,0),HH-1);
    const int cx0 = min(max(x0,0),WW-1), cx1 = min(max(x1,0),WW-1);
    const int i00 = cy0*WW+cx0, i01 = cy0*WW+cx1, i10 = cy1*WW+cx0, i11 = cy1*WW+cx1;

    const float* xb = x + b * (CIN*HW);
    const int m = b*HW + h*WW + w;
    const int kkbase = k * CIN;

#pragma unroll 4
    for (int c = 0; c < CIN; c++) {
        const float* xp = xb + c*HW;
        float v = w00*xp[i00] + w01*xp[i01] + w10*xp[i10] + w11*xp[i11];
        g_A[(kkbase + c)*MTOT + m] = v;
    }
}

// ---------------------------------------------------------------- weight repack
// Wt[(k*CIN+c)*COUT + o] = conv_w[o][c][k]   (conv_w: [Cout,Cin,3,3], k=ky*3+kx)
__global__ void repack_w_kernel(const float* __restrict__ cw) {
    int i = blockIdx.x * 256 + threadIdx.x;   // over KKTOT*COUT = 589824
    if (i >= KKTOT*COUT) return;
    int o  = i & 255;
    int kk = i >> 8;
    int c  = kk & 255;
    int k  = kk >> 8;
    g_Wt[i] = cw[(o*CIN + c)*9 + k];
}

// ---------------------------------------------------------------- main GEMM
// O[m][o] = sum_kk A^T[kk][m] * Wt[kk][o]
// BM=128, BN=64, BK=16, 256 threads, 8x4 microtile. Fused GN partial sums.
__global__ void gemm_kernel() {
    __shared__ float As[16][128];
    __shared__ float Bs[16][64];
    __shared__ float sred[8][2];

    const int m0 = blockIdx.x * 128;
    const int n0 = blockIdx.y * 64;
    const int tid = threadIdx.x;            // 0..255
    const int ty = tid >> 4;                // 0..15 -> m rows (x8)
    const int tx = tid & 15;                // 0..15 -> n cols (x4)

    // A load mapping: 2 float4 per thread
    const int arow = tid >> 5;              // 0..7
    const int acol = (tid & 31) * 4;        // 0..124
    // B load mapping: 1 float4 per thread
    const int brow = tid >> 4;              // 0..15
    const int bcol = (tid & 15) * 4;        // 0..60

    float acc[8][4];
#pragma unroll
    for (int i = 0; i < 8; i++)
#pragma unroll
        for (int j = 0; j < 4; j++) acc[i][j] = 0.f;

    for (int kk0 = 0; kk0 < KKTOT; kk0 += 16) {
        *(float4*)&As[arow    ][acol] = *(const float4*)&g_A[(kk0 + arow    )*MTOT + m0 + acol];
        *(float4*)&As[arow + 8][acol] = *(const float4*)&g_A[(kk0 + arow + 8)*MTOT + m0 + acol];
        *(float4*)&Bs[brow][bcol]     = *(const float4*)&g_Wt[(kk0 + brow)*COUT + n0 + bcol];
        __syncthreads();

#pragma unroll
        for (int p = 0; p < 16; p++) {
            float a[8], bv[4];
            *(float4*)&a[0] = *(float4*)&As[p][ty*8];
            *(float4*)&a[4] = *(float4*)&As[p][ty*8+4];
            *(float4*)&bv[0] = *(float4*)&Bs[p][tx*4];
#pragma unroll
            for (int i = 0; i < 8; i++)
#pragma unroll
                for (int j = 0; j < 4; j++) acc[i][j] += a[i] * bv[j];
        }
        __syncthreads();
    }

    // Epilogue: write O (NHWC) + GN partial sums
    float s = 0.f, s2 = 0.f;
#pragma unroll
    for (int i = 0; i < 8; i++) {
        int m = m0 + ty*8 + i;
        float4 v = make_float4(acc[i][0], acc[i][1], acc[i][2], acc[i][3]);
        *(float4*)&g_O[m*COUT + n0 + tx*4] = v;
        s  += v.x + v.y + v.z + v.w;
        s2 += v.x*v.x + v.y*v.y + v.z*v.z + v.w*v.w;
    }

    if (tid < 16) ((float*)sred)[tid] = 0.f;
    __syncthreads();
    const int gl = tx >> 1;   // (tx*4)/8 : local group 0..7 (4 cols never straddle a group)
    atomicAdd(&sred[gl][0], s);
    atomicAdd(&sred[gl][1], s2);
    __syncthreads();
    if (tid < 16) {
        int g = tid >> 1, comp = tid & 1;
        int bidx = m0 / HW;                 // tile never straddles b (HW % 128 == 0)
        int gidx = n0/GCH + g;
        atomicAdd(&g_stats[(bidx*NGRP + gidx)*2 + comp], sred[g][comp]);
    }
}

// ---------------------------------------------------------------- GN + ReLU + NHWC->NCHW
__global__ void norm_kernel(float* __restrict__ out,
                            const float* __restrict__ gamma,
                            const float* __restrict__ beta) {
    int idx = blockIdx.x * 256 + threadIdx.x;   // over B*Cout*HW = 4718592
    if (idx >= BB*COUT*HW) return;
    int w = idx % WW; int t = idx / WW;
    int h = t % HH;  t /= HH;
    int o = t % COUT;
    int b = t / COUT;
    int g = o >> 3;

    float s  = g_stats[(b*NGRP + g)*2 + 0];
    float s2 = g_stats[(b*NGRP + g)*2 + 1];
    float mu  = s  * (1.f / (float)GELEMS);
    float var = s2 * (1.f / (float)GELEMS) - mu*mu;
    float rinv = rsqrtf(var + 1e-5f);

    float v = g_O[(b*HW + h*WW + w)*COUT + o];
    v = (v - mu) * rinv * gamma[o] + beta[o];
    out[idx] = fmaxf(v, 0.f);
}

// ---------------------------------------------------------------- launch
extern "C" void kernel_launch(void* const* d_in, const int* in_sizes, int n_in,
                              void* d_out, int out_size) {
    const float* x     = (const float*)d_in[0];
    const float* off_w = (const float*)d_in[1];
    const float* off_b = (const float*)d_in[2];
    const float* cw    = (const float*)d_in[3];
    const float* gamma = (const float*)d_in[4];
    const float* beta  = (const float*)d_in[5];
    float* out = (float*)d_out;

    zero_stats_kernel<<<1, 128>>>();
    offset_conv_kernel<<<dim3(WW/32, HH/4, BB), dim3(32, 4)>>>(x, off_w, off_b);
    repack_w_kernel<<<(KKTOT*COUT + 255)/256, 256>>>(cw);
    gather_kernel<<<dim3(HH, KK2, BB), WW>>>(x);
    gemm_kernel<<<dim3(MTOT/128, COUT/64), 256>>>();
    norm_kernel<<<(BB*COUT*HW + 255)/256, 256>>>(out, gamma, beta);
}

// round 3
// speedup vs baseline: 1.2650x; 1.2650x over previous
#include <cuda_runtime.h>
#include <cstdint>

// Problem constants
#define BB 2
#define CIN 256
#define HH 96
#define WW 96
#define COUT 256
#define KK2 9
#define HW (HH*WW)                 // 9216
#define MTOT (BB*HW)               // 18432
#define KKTOT (KK2*CIN)            // 2304
#define NGRP 32
#define GCH (COUT/NGRP)            // 8
#define GELEMS (GCH*HW)            // 73728
#define NIT (KKTOT/32)             // 72 mainloop iters (BK=32)
#define NKS (KKTOT/8)              // 288 k8 steps

// Scratch (static device memory)
__device__ __align__(128) float g_off[BB*18*HW];          // offsets  [B,18,H,W]
__device__ __align__(128) float g_A[(size_t)KKTOT*MTOT];  // im2col A^T: [KK, M]
__device__ __align__(128) float g_Wfh[NKS*32*64];         // B hi, fragment order [k8][n8][lane][2]
__device__ __align__(128) float g_Wfl[NKS*32*64];         // B lo
__device__ __align__(128) float g_O[(size_t)MTOT*COUT];   // GEMM out (NHWC): [M, Cout]
__device__ __align__(128) float g_stats[NGRP*BB*2];       // per (b,g): sum, sumsq

// ------------------------------------------------------------- helpers
__device__ __forceinline__ uint32_t tf32_hi_bits(float a) {
    return __float_as_uint(a) & 0xFFFFE000u;
}

#define CP_ASYNC16(dst, src) \
    asm volatile("cp.async.cg.shared.global [%0], [%1], 16;" \
                 :: "r"((uint32_t)(dst)), "l"(__cvta_generic_to_global(src)) : "memory")
#define CP_COMMIT() asm volatile("cp.async.commit_group;" ::: "memory")
#define CP_WAIT0()  asm volatile("cp.async.wait_group 0;" ::: "memory")

__device__ __forceinline__ uint32_t smem_u32(const void* p) {
    uint32_t a;
    asm("{ .reg .u64 t; cvta.to.shared.u64 t, %1; cvt.u32.u64 %0, t; }"
        : "=r"(a) : "l"(p));
    return a;
}

#define MMA_TF32(acc, a, b0, b1) \
    asm volatile("mma.sync.aligned.m16n8k8.row.col.f32.tf32.tf32.f32 " \
                 "{%0,%1,%2,%3},{%4,%5,%6,%7},{%8,%9},{%0,%1,%2,%3};" \
                 : "+f"((acc)[0]), "+f"((acc)[1]), "+f"((acc)[2]), "+f"((acc)[3]) \
                 : "r"((a)[0]), "r"((a)[1]), "r"((a)[2]), "r"((a)[3]), \
                   "r"(b0), "r"(b1))

// ---------------------------------------------------------------- zero stats
__global__ void zero_stats_kernel() {
    int i = threadIdx.x;
    if (i < NGRP*BB*2) g_stats[i] = 0.f;
}

// ---------------------------------------------------------------- offset conv
__global__ void offset_conv_kernel(const float* __restrict__ x,
                                   const float* __restrict__ ow,
                                   const float* __restrict__ ob) {
    __shared__ float xs[6][34];
    __shared__ __align__(16) float ws[9][20];   // [tap][out j], padded rows
    const int w0 = blockIdx.x * 32;
    const int h0 = blockIdx.y * 4;
    const int b  = blockIdx.z;
    const int tx = threadIdx.x, ty = threadIdx.y;
    const int tid = ty * 32 + tx;

    float acc[18];
#pragma unroll
    for (int j = 0; j < 18; j++) acc[j] = 0.f;

    const float* xb = x + b * (CIN*HW);

    for (int c = 0; c < CIN; c++) {
        for (int i = tid; i < 6*34; i += 128) {
            int r = i / 34, cc = i % 34;
            int y = h0 - 1 + r, xx = w0 - 1 + cc;
            float v = 0.f;
            if (y >= 0 && y < HH && xx >= 0 && xx < WW) v = xb[c*HW + y*WW + xx];
            xs[r][cc] = v;
        }
        for (int i = tid; i < 162; i += 128) {
            int j = i / 9, t = i % 9;
            ws[t][j] = ow[j*(CIN*9) + c*9 + t];
        }
        __syncthreads();

#pragma unroll
        for (int t = 0; t < 9; t++) {
            float xv = xs[ty + t/3][tx + t%3];
            float4 a0 = *(const float4*)&ws[t][0];
            float4 a1 = *(const float4*)&ws[t][4];
            float4 a2 = *(const float4*)&ws[t][8];
            float4 a3 = *(const float4*)&ws[t][12];
            float  a4 = ws[t][16], a5 = ws[t][17];
            acc[0]  += xv*a0.x; acc[1]  += xv*a0.y; acc[2]  += xv*a0.z; acc[3]  += xv*a0.w;
            acc[4]  += xv*a1.x; acc[5]  += xv*a1.y; acc[6]  += xv*a1.z; acc[7]  += xv*a1.w;
            acc[8]  += xv*a2.x; acc[9]  += xv*a2.y; acc[10] += xv*a2.z; acc[11] += xv*a2.w;
            acc[12] += xv*a3.x; acc[13] += xv*a3.y; acc[14] += xv*a3.z; acc[15] += xv*a3.w;
            acc[16] += xv*a4;   acc[17] += xv*a5;
        }
        __syncthreads();
    }
    const int h = h0 + ty, w = w0 + tx;
#pragma unroll
    for (int j = 0; j < 18; j++)
        g_off[((b*18 + j)*HH + h)*WW + w] = acc[j] + ob[j];
}

// ---------------------------------------------------------------- gather/im2col (A^T: [kk][m])
__global__ void gather_kernel(const float* __restrict__ x) {
    const int w = threadIdx.x;        // 0..95
    const int h = blockIdx.x;         // 0..95
    const int k = blockIdx.y;         // 0..8
    const int b = blockIdx.z;         // 0..1

    const int off_base = ((b*18 + 2*k)*HH + h)*WW + w;
    const float dy = g_off[off_base];
    const float dx = g_off[off_base + HW];

    const float sy = (float)(h - 1 + k/3) + dy;
    const float sx = (float)(w - 1 + k%3) + dx;
    const float y0f = floorf(sy), x0f = floorf(sx);
    const float fy = sy - y0f, fx = sx - x0f;
    const int y0 = (int)y0f, x0 = (int)x0f;
    const int y1 = y0 + 1,  x1 = x0 + 1;

    const bool vy0 = (y0 >= 0) && (y0 < HH), vy1 = (y1 >= 0) && (y1 < HH);
    const bool vx0 = (x0 >= 0) && (x0 < WW), vx1 = (x1 >= 0) && (x1 < WW);
    const float w00 = (vy0 && vx0) ? (1.f-fy)*(1.f-fx) : 0.f;
    const float w01 = (vy0 && vx1) ? (1.f-fy)*fx       : 0.f;
    const float w10 = (vy1 && vx0) ? fy*(1.f-fx)       : 0.f;
    const float w11 = (vy1 && vx1) ? fy*fx             : 0.f;

    const int cy0 = min(max(y0,0),HH-1), cy1 = min(max(y1,0),HH-1);
    const int cx0 = min(max(x0,0),WW-1), cx1 = min(max(x1,0),WW-1);
    const int i00 = cy0*WW+cx0, i01 = cy0*WW+cx1, i10 = cy1*WW+cx0, i11 = cy1*WW+cx1;

    const float* xb = x + b * (CIN*HW);
    const int m = b*HW + h*WW + w;
    const int kkbase = k * CIN;

#pragma unroll 4
    for (int c = 0; c < CIN; c++) {
        const float* xp = xb + c*HW;
        float v = w00*xp[i00] + w01*xp[i01] + w10*xp[i10] + w11*xp[i11];
        g_A[(size_t)(kkbase + c)*MTOT + m] = v;
    }
}

// ---------------------------------------------------------------- weight repack into mma fragment order + hi/lo split
// g_Wf{h,l}[((k8*32 + n8)*32 + lane)*2 + j]:
//   kk = k8*8 + (lane&3) + 4*j, n = n8*8 + (lane>>2)
//   kk = tap*256 + c  -> value = cw[(n*CIN + c)*9 + tap]
__global__ void repack_w_kernel(const float* __restrict__ cw) {
    int idx = blockIdx.x * 256 + threadIdx.x;   // over NKS*32*64 = 589824
    if (idx >= NKS*32*64) return;
    int j    = idx & 1;
    int lane = (idx >> 1) & 31;
    int n8   = (idx >> 6) & 31;
    int k8   = idx >> 11;
    int kk = k8*8 + (lane & 3) + 4*j;
    int n  = n8*8 + (lane >> 2);
    int c  = kk & 255;
    int tap = kk >> 8;
    float v = cw[(n*CIN + c)*9 + tap];
    uint32_t hb = tf32_hi_bits(v);
    float hv = __uint_as_float(hb);
    g_Wfh[idx] = hv;
    g_Wfl[idx] = v - hv;
}

// ---------------------------------------------------------------- main GEMM: 3xTF32 mma.sync
// BM=128 (grid.x = 144), BN=256 (all Cout), BK=32 (4 k8 steps), 512 threads.
// Warp grid 4(m) x 4(n): warp tile 32 x 64 -> mt=2, nt=8, acc[2][8][4].
// B in smem (fragment order, hi/lo), double-buffered via cp.async.
// A fragments direct from g_A via LDG, 1-kstep register prefetch.
#define STAGE_BYTES 65536            // 32KB hi + 32KB lo per BK=32 stage
#define SMEM_BYTES  (2*STAGE_BYTES + 256)

__global__ __launch_bounds__(512) void gemm_kernel() {
    extern __shared__ char smem[];
    float* sred = (float*)(smem + 2*STAGE_BYTES);
    const uint32_t sb = smem_u32(smem);
    const int tid = threadIdx.x, lane = tid & 31, wid = tid >> 5;
    const int wm = wid & 3, wn = wid >> 2;
    const int m0 = blockIdx.x * 128;
    const int b = m0 / HW;

    if (tid < 64) sred[tid] = 0.f;

    float acc[2][8][4];
#pragma unroll
    for (int i = 0; i < 2; i++)
#pragma unroll
        for (int j = 0; j < 8; j++)
#pragma unroll
            for (int e = 0; e < 4; e++) acc[i][j][e] = 0.f;

    // A fragment element offsets (mt=0; mt=1 adds +16)
    uint32_t aoffs[4];
    {
        const int mbase = m0 + wm*32 + (lane >> 2);
#pragma unroll
        for (int r = 0; r < 4; r++)
            aoffs[r] = (uint32_t)(((lane & 3) + ((r & 2) << 1)) * MTOT + mbase + (r & 1)*8);
    }

    // B stage fill: flat 32KB hi + 32KB lo, contiguous in fragment-order arrays
    auto issueB = [&](int s, int q) {
        const float* srcH = g_Wfh + (size_t)q * 8192;
        const float* srcL = g_Wfl + (size_t)q * 8192;
        const uint32_t dH = sb + s*STAGE_BYTES + tid*64;
        const uint32_t dL = dH + 32768;
#pragma unroll
        for (int j = 0; j < 4; j++) {
            CP_ASYNC16(dH + j*16, srcH + tid*16 + j*4);
            CP_ASYNC16(dL + j*16, srcL + tid*16 + j*4);
        }
    };

    float va[2][2][4];
    // prefetch t=0
#pragma unroll
    for (int mt = 0; mt < 2; mt++)
#pragma unroll
        for (int r = 0; r < 4; r++)
            va[0][mt][r] = g_A[(size_t)aoffs[r] + mt*16];

    issueB(0, 0); CP_COMMIT();

    int t = 0;
    for (int q = 0; q < NIT; q++) {
        CP_WAIT0();
        __syncthreads();
        if (q + 1 < NIT) { issueB((q + 1) & 1, q + 1); CP_COMMIT(); }
        const int p = q & 1;

#pragma unroll
        for (int ks = 0; ks < 4; ks++, t++) {
            const int buf = t & 1;
            // prefetch next kstep's A fragments
            if (t + 1 < NKS) {
                const float* pA = g_A + (size_t)(t + 1) * (8*MTOT);
#pragma unroll
                for (int mt = 0; mt < 2; mt++)
#pragma unroll
                    for (int r = 0; r < 4; r++)
                        va[buf ^ 1][mt][r] = pA[(size_t)aoffs[r] + mt*16];
            }
            // split A into hi/lo
            uint32_t ah[2][4], al[2][4];
#pragma unroll
            for (int mt = 0; mt < 2; mt++)
#pragma unroll
                for (int r = 0; r < 4; r++) {
                    float v = va[buf][mt][r];
                    uint32_t hb = tf32_hi_bits(v);
                    ah[mt][r] = hb;
                    al[mt][r] = __float_as_uint(v - __uint_as_float(hb));
                }
            // B frags + MMA
            const char* bbase = smem + p*STAGE_BYTES + ks*8192 + lane*8;
#pragma unroll
            for (int nt = 0; nt < 8; nt++) {
                const int ng = wn*8 + nt;
                float2 bh = *reinterpret_cast<const float2*>(bbase + ng*256);
                float2 bl = *reinterpret_cast<const float2*>(bbase + ng*256 + 32768);
                uint32_t bh0 = __float_as_uint(bh.x), bh1 = __float_as_uint(bh.y);
                uint32_t bl0 = __float_as_uint(bl.x), bl1 = __float_as_uint(bl.y);
#pragma unroll
                for (int mt = 0; mt < 2; mt++) {
                    MMA_TF32(acc[mt][nt], ah[mt], bh0, bh1);
                    MMA_TF32(acc[mt][nt], ah[mt], bl0, bl1);
                    MMA_TF32(acc[mt][nt], al[mt], bh0, bh1);
                }
            }
        }
    }

    // Epilogue: write g_O (NHWC) + GN partial sums
    const int mrow = m0 + wm*32 + (lane >> 2);
#pragma unroll
    for (int nt = 0; nt < 8; nt++) {
        const int ng = wn*8 + nt;
        const int n = wn*64 + nt*8 + 2*(lane & 3);
        float s = 0.f, s2 = 0.f;
#pragma unroll
        for (int mt = 0; mt < 2; mt++) {
            float* a4 = acc[mt][nt];
            const int m1 = mrow + mt*16;
            *reinterpret_cast<float2*>(&g_O[(size_t)m1*COUT + n])       = make_float2(a4[0], a4[1]);
            *reinterpret_cast<float2*>(&g_O[(size_t)(m1 + 8)*COUT + n]) = make_float2(a4[2], a4[3]);
            s  += a4[0] + a4[1] + a4[2] + a4[3];
            s2 += a4[0]*a4[0] + a4[1]*a4[1] + a4[2]*a4[2] + a4[3]*a4[3];
        }
#pragma unroll
        for (int o = 16; o > 0; o >>= 1) {
            s  += __shfl_down_sync(0xFFFFFFFFu, s,  o);
            s2 += __shfl_down_sync(0xFFFFFFFFu, s2, o);
        }
        if (lane == 0) {
            atomicAdd(&sred[ng*2 + 0], s);
            atomicAdd(&sred[ng*2 + 1], s2);
        }
    }
    __syncthreads();
    if (tid < 64) atomicAdd(&g_stats[b*64 + tid], sred[tid]);
}

// ---------------------------------------------------------------- GN + ReLU + NHWC->NCHW
__global__ void norm_kernel(float* __restrict__ out,
                            const float* __restrict__ gamma,
                            const float* __restrict__ beta) {
    int idx = blockIdx.x * 256 + threadIdx.x;
    if (idx >= BB*COUT*HW) return;
    int w = idx % WW; int t = idx / WW;
    int h = t % HH;  t /= HH;
    int o = t % COUT;
    int b = t / COUT;
    int g = o >> 3;

    float s  = g_stats[(b*NGRP + g)*2 + 0];
    float s2 = g_stats[(b*NGRP + g)*2 + 1];
    float mu  = s  * (1.f / (float)GELEMS);
    float var = s2 * (1.f / (float)GELEMS) - mu*mu;
    float rinv = rsqrtf(var + 1e-5f);

    float v = g_O[(size_t)(b*HW + h*WW + w)*COUT + o];
    v = (v - mu) * rinv * gamma[o] + beta[o];
    out[idx] = fmaxf(v, 0.f);
}

// ---------------------------------------------------------------- launch
extern "C" void kernel_launch(void* const* d_in, const int* in_sizes, int n_in,
                              void* d_out, int out_size) {
    const float* x     = (const float*)d_in[0];
    const float* off_w = (const float*)d_in[1];
    const float* off_b = (const float*)d_in[2];
    const float* cw    = (const float*)d_in[3];
    const float* gamma = (const float*)d_in[4];
    const float* beta  = (const float*)d_in[5];
    float* out = (float*)d_out;

    cudaFuncSetAttribute(gemm_kernel,
                         cudaFuncAttributeMaxDynamicSharedMemorySize, SMEM_BYTES);

    zero_stats_kernel<<<1, 128>>>();
    offset_conv_kernel<<<dim3(WW/32, HH/4, BB), dim3(32, 4)>>>(x, off_w, off_b);
    repack_w_kernel<<<(NKS*32*64 + 255)/256, 256>>>(cw);
    gather_kernel<<<dim3(HH, KK2, BB), WW>>>(x);
    gemm_kernel<<<MTOT/128, 512, SMEM_BYTES>>>();
    norm_kernel<<<(BB*COUT*HW + 255)/256, 256>>>(out, gamma, beta);
}

// round 4
// speedup vs baseline: 1.5839x; 1.2521x over previous
#include <cuda_runtime.h>
#include <cuda_bf16.h>
#include <cstdint>

// Problem constants
#define BB 2
#define CIN 256
#define HH 96
#define WW 96
#define COUT 256
#define KK2 9
#define HW (HH*WW)                 // 9216
#define MTOT (BB*HW)               // 18432
#define KKTOT (KK2*CIN)            // 2304
#define NGRP 32
#define GCH (COUT/NGRP)            // 8
#define GELEMS (GCH*HW)            // 73728
#define NPAIR (KKTOT/2)            // 1152 kk-pairs
#define NK16 (KKTOT/16)            // 144 k16 steps
#define NST (KKTOT/32)             // 72 BK=32 stages

// Scratch (static device memory)
__device__ __align__(128) float    g_off[BB*18*HW];            // offsets  [B,18,H,W]
__device__ __align__(128) uint32_t g_Aph[(size_t)NPAIR*MTOT];  // A hi, bf16x2 packed [pair][m]
__device__ __align__(128) uint32_t g_Apl[(size_t)NPAIR*MTOT];  // A lo
__device__ __align__(128) uint32_t g_Wfbh[NK16*32*32*2];       // B hi frag order [k16][n8][lane][2]
__device__ __align__(128) uint32_t g_Wfbl[NK16*32*32*2];       // B lo
__device__ __align__(128) float    g_O[(size_t)MTOT*COUT];     // GEMM out (NHWC): [M, Cout]
__device__ __align__(128) float    g_stats[NGRP*BB*2];         // per (b,g): sum, sumsq

// ------------------------------------------------------------- helpers
__device__ __forceinline__ uint32_t pack2_bf16(float a, float b) {
    uint16_t ua = __bfloat16_as_ushort(__float2bfloat16(a));
    uint16_t ub = __bfloat16_as_ushort(__float2bfloat16(b));
    return (uint32_t)ua | ((uint32_t)ub << 16);
}

#define CP_ASYNC16(dst, src) \
    asm volatile("cp.async.cg.shared.global [%0], [%1], 16;" \
                 :: "r"((uint32_t)(dst)), "l"(__cvta_generic_to_global(src)) : "memory")
#define CP_COMMIT() asm volatile("cp.async.commit_group;" ::: "memory")
#define CP_WAIT0()  asm volatile("cp.async.wait_group 0;" ::: "memory")

__device__ __forceinline__ uint32_t smem_u32(const void* p) {
    uint32_t a;
    asm("{ .reg .u64 t; cvta.to.shared.u64 t, %1; cvt.u32.u64 %0, t; }"
        : "=r"(a) : "l"(p));
    return a;
}

#define MMA_BF16(acc, a, b0, b1) \
    asm volatile("mma.sync.aligned.m16n8k16.row.col.f32.bf16.bf16.f32 " \
                 "{%0,%1,%2,%3},{%4,%5,%6,%7},{%8,%9},{%0,%1,%2,%3};" \
                 : "+f"((acc)[0]), "+f"((acc)[1]), "+f"((acc)[2]), "+f"((acc)[3]) \
                 : "r"((a)[0]), "r"((a)[1]), "r"((a)[2]), "r"((a)[3]), \
                   "r"(b0), "r"(b1))

// ---------------------------------------------------------------- zero stats
__global__ void zero_stats_kernel() {
    int i = threadIdx.x;
    if (i < NGRP*BB*2) g_stats[i] = 0.f;
}

// ---------------------------------------------------------------- offset conv
__global__ void offset_conv_kernel(const float* __restrict__ x,
                                   const float* __restrict__ ow,
                                   const float* __restrict__ ob) {
    __shared__ float xs[6][34];
    __shared__ __align__(16) float ws[9][20];
    const int w0 = blockIdx.x * 32;
    const int h0 = blockIdx.y * 4;
    const int b  = blockIdx.z;
    const int tx = threadIdx.x, ty = threadIdx.y;
    const int tid = ty * 32 + tx;

    float acc[18];
#pragma unroll
    for (int j = 0; j < 18; j++) acc[j] = 0.f;

    const float* xb = x + b * (CIN*HW);

    for (int c = 0; c < CIN; c++) {
        for (int i = tid; i < 6*34; i += 128) {
            int r = i / 34, cc = i % 34;
            int y = h0 - 1 + r, xx = w0 - 1 + cc;
            float v = 0.f;
            if (y >= 0 && y < HH && xx >= 0 && xx < WW) v = xb[c*HW + y*WW + xx];
            xs[r][cc] = v;
        }
        for (int i = tid; i < 162; i += 128) {
            int j = i / 9, t = i % 9;
            ws[t][j] = ow[j*(CIN*9) + c*9 + t];
        }
        __syncthreads();

#pragma unroll
        for (int t = 0; t < 9; t++) {
            float xv = xs[ty + t/3][tx + t%3];
            float4 a0 = *(const float4*)&ws[t][0];
            float4 a1 = *(const float4*)&ws[t][4];
            float4 a2 = *(const float4*)&ws[t][8];
            float4 a3 = *(const float4*)&ws[t][12];
            float  a4 = ws[t][16], a5 = ws[t][17];
            acc[0]  += xv*a0.x; acc[1]  += xv*a0.y; acc[2]  += xv*a0.z; acc[3]  += xv*a0.w;
            acc[4]  += xv*a1.x; acc[5]  += xv*a1.y; acc[6]  += xv*a1.z; acc[7]  += xv*a1.w;
            acc[8]  += xv*a2.x; acc[9]  += xv*a2.y; acc[10] += xv*a2.z; acc[11] += xv*a2.w;
            acc[12] += xv*a3.x; acc[13] += xv*a3.y; acc[14] += xv*a3.z; acc[15] += xv*a3.w;
            acc[16] += xv*a4;   acc[17] += xv*a5;
        }
        __syncthreads();
    }
    const int h = h0 + ty, w = w0 + tx;
#pragma unroll
    for (int j = 0; j < 18; j++)
        g_off[((b*18 + j)*HH + h)*WW + w] = acc[j] + ob[j];
}

// ---------------------------------------------------------------- gather/im2col -> bf16 hi/lo packed pairs
__global__ void gather_kernel(const float* __restrict__ x) {
    const int w = threadIdx.x;        // 0..95
    const int h = blockIdx.x;         // 0..95
    const int k = blockIdx.y;         // 0..8
    const int b = blockIdx.z;         // 0..1

    const int off_base = ((b*18 + 2*k)*HH + h)*WW + w;
    const float dy = g_off[off_base];
    const float dx = g_off[off_base + HW];

    const float sy = (float)(h - 1 + k/3) + dy;
    const float sx = (float)(w - 1 + k%3) + dx;
    const float y0f = floorf(sy), x0f = floorf(sx);
    const float fy = sy - y0f, fx = sx - x0f;
    const int y0 = (int)y0f, x0 = (int)x0f;
    const int y1 = y0 + 1,  x1 = x0 + 1;

    const bool vy0 = (y0 >= 0) && (y0 < HH), vy1 = (y1 >= 0) && (y1 < HH);
    const bool vx0 = (x0 >= 0) && (x0 < WW), vx1 = (x1 >= 0) && (x1 < WW);
    const float w00 = (vy0 && vx0) ? (1.f-fy)*(1.f-fx) : 0.f;
    const float w01 = (vy0 && vx1) ? (1.f-fy)*fx       : 0.f;
    const float w10 = (vy1 && vx0) ? fy*(1.f-fx)       : 0.f;
    const float w11 = (vy1 && vx1) ? fy*fx             : 0.f;

    const int cy0 = min(max(y0,0),HH-1), cy1 = min(max(y1,0),HH-1);
    const int cx0 = min(max(x0,0),WW-1), cx1 = min(max(x1,0),WW-1);
    const int i00 = cy0*WW+cx0, i01 = cy0*WW+cx1, i10 = cy1*WW+cx0, i11 = cy1*WW+cx1;

    const float* xb = x + b * (CIN*HW);
    const int m = b*HW + h*WW + w;
    const int pbase = k * 128;        // pair base for this tap

#pragma unroll 2
    for (int cp = 0; cp < 128; cp++) {
        const float* xp0 = xb + (size_t)(2*cp)     * HW;
        const float* xp1 = xb + (size_t)(2*cp + 1) * HW;
        float v0 = w00*xp0[i00] + w01*xp0[i01] + w10*xp0[i10] + w11*xp0[i11];
        float v1 = w00*xp1[i00] + w01*xp1[i01] + w10*xp1[i10] + w11*xp1[i11];
        float h0 = __bfloat162float(__float2bfloat16(v0));
        float h1 = __bfloat162float(__float2bfloat16(v1));
        g_Aph[(size_t)(pbase + cp)*MTOT + m] = pack2_bf16(h0, h1);
        g_Apl[(size_t)(pbase + cp)*MTOT + m] = pack2_bf16(v0 - h0, v1 - h1);
    }
}

// ---------------------------------------------------------------- weight repack: bf16 hi/lo, mma fragment order
// idx = [k16][n8][lane][reg]; reg j in {0,1} (b0 = k rows 2*(lane&3)+{0,1}, b1 = +8)
__global__ void repack_w_kernel(const float* __restrict__ cw) {
    int idx = blockIdx.x * 256 + threadIdx.x;   // over NK16*32*32*2 = 294912
    if (idx >= NK16*32*32*2) return;
    int j    = idx & 1;
    int lane = (idx >> 1) & 31;
    int n8   = (idx >> 6) & 31;
    int k16  = idx >> 11;
    int kk0 = k16*16 + j*8 + 2*(lane & 3);
    int n   = n8*8 + (lane >> 2);
    int c0 = kk0 & 255, tap0 = kk0 >> 8;
    int kk1 = kk0 + 1;
    int c1 = kk1 & 255, tap1 = kk1 >> 8;
    float v0 = cw[(n*CIN + c0)*9 + tap0];
    float v1 = cw[(n*CIN + c1)*9 + tap1];
    float h0 = __bfloat162float(__float2bfloat16(v0));
    float h1 = __bfloat162float(__float2bfloat16(v1));
    g_Wfbh[idx] = pack2_bf16(h0, h1);
    g_Wfbl[idx] = pack2_bf16(v0 - h0, v1 - h1);
}

// ---------------------------------------------------------------- main GEMM: 3xBF16 m16n8k16
// BM=128 (grid=144), BN=256, BK=32 (2 k16 steps/stage), 512 threads, warp 32x64.
#define STAGE_BYTES 32768            // [hi 16KB: [k16in][ng][lane][2]][lo 16KB]
#define SMEM_BYTES  (2*STAGE_BYTES + 256)

__global__ __launch_bounds__(512, 1) void gemm_kernel() {
    extern __shared__ char smem[];
    float* sred = (float*)(smem + 2*STAGE_BYTES);
    const uint32_t sb = smem_u32(smem);
    const int tid = threadIdx.x, lane = tid & 31, wid = tid >> 5;
    const int wm = wid & 3, wn = wid >> 2;
    const int m0 = blockIdx.x * 128;
    const int b = m0 / HW;

    if (tid < 64) sred[tid] = 0.f;

    float acc[2][8][4];
#pragma unroll
    for (int i = 0; i < 2; i++)
#pragma unroll
        for (int j = 0; j < 8; j++)
#pragma unroll
            for (int e = 0; e < 4; e++) acc[i][j][e] = 0.f;

    const int mb = m0 + wm*32 + (lane >> 2);
    const size_t o0 = (size_t)(lane & 3)*MTOT + mb;

    uint32_t vah[2][2][4], val[2][2][4];

    auto loadA = [&](int t, int buf) {
        const uint32_t* ph = g_Aph + (size_t)t*8*MTOT;
        const uint32_t* pl = g_Apl + (size_t)t*8*MTOT;
#pragma unroll
        for (int mt = 0; mt < 2; mt++) {
            size_t base = o0 + mt*16;
            vah[buf][mt][0] = ph[base];
            vah[buf][mt][1] = ph[base + 8];
            vah[buf][mt][2] = ph[base + 4*(size_t)MTOT];
            vah[buf][mt][3] = ph[base + 4*(size_t)MTOT + 8];
            val[buf][mt][0] = pl[base];
            val[buf][mt][1] = pl[base + 8];
            val[buf][mt][2] = pl[base + 4*(size_t)MTOT];
            val[buf][mt][3] = pl[base + 4*(size_t)MTOT + 8];
        }
    };

    auto issueB = [&](int s, int q) {
        const uint32_t* srcH = g_Wfbh + (size_t)q * 4096;
        const uint32_t* srcL = g_Wfbl + (size_t)q * 4096;
        const uint32_t dH = sb + s*STAGE_BYTES + tid*16;
#pragma unroll
        for (int j = 0; j < 2; j++) {
            CP_ASYNC16(dH + j*8192,         srcH + tid*4 + j*2048);
            CP_ASYNC16(dH + 16384 + j*8192, srcL + tid*4 + j*2048);
        }
    };

    loadA(0, 0);
    issueB(0, 0); CP_COMMIT();

    for (int q = 0; q < NST; q++) {
        CP_WAIT0();
        __syncthreads();
        if (q + 1 < NST) { issueB((q + 1) & 1, q + 1); CP_COMMIT(); }
        const int p = q & 1;

#pragma unroll
        for (int ks = 0; ks < 2; ks++) {
            const int t = q*2 + ks;
            const int buf = t & 1;
            if (t + 1 < NK16) loadA(t + 1, buf ^ 1);

            const char* bb = smem + p*STAGE_BYTES + ks*8192 + lane*8;
#pragma unroll
            for (int nt = 0; nt < 8; nt++) {
                const int ng = wn*8 + nt;
                uint2 bh = *reinterpret_cast<const uint2*>(bb + ng*256);
                uint2 bl = *reinterpret_cast<const uint2*>(bb + ng*256 + 16384);
#pragma unroll
                for (int mt = 0; mt < 2; mt++) {
                    MMA_BF16(acc[mt][nt], vah[buf][mt], bh.x, bh.y);
                    MMA_BF16(acc[mt][nt], vah[buf][mt], bl.x, bl.y);
                    MMA_BF16(acc[mt][nt], val[buf][mt], bh.x, bh.y);
                }
            }
        }
    }

    // Epilogue: write g_O (NHWC) + GN partial sums
    const int mrow = m0 + wm*32 + (lane >> 2);
#pragma unroll
    for (int nt = 0; nt < 8; nt++) {
        const int ng = wn*8 + nt;
        const int n = wn*64 + nt*8 + 2*(lane & 3);
        float s = 0.f, s2 = 0.f;
#pragma unroll
        for (int mt = 0; mt < 2; mt++) {
            float* a4 = acc[mt][nt];
            const int m1 = mrow + mt*16;
            *reinterpret_cast<float2*>(&g_O[(size_t)m1*COUT + n])       = make_float2(a4[0], a4[1]);
            *reinterpret_cast<float2*>(&g_O[(size_t)(m1 + 8)*COUT + n]) = make_float2(a4[2], a4[3]);
            s  += a4[0] + a4[1] + a4[2] + a4[3];
            s2 += a4[0]*a4[0] + a4[1]*a4[1] + a4[2]*a4[2] + a4[3]*a4[3];
        }
#pragma unroll
        for (int o = 16; o > 0; o >>= 1) {
            s  += __shfl_down_sync(0xFFFFFFFFu, s,  o);
            s2 += __shfl_down_sync(0xFFFFFFFFu, s2, o);
        }
        if (lane == 0) {
            atomicAdd(&sred[ng*2 + 0], s);
            atomicAdd(&sred[ng*2 + 1], s2);
        }
    }
    __syncthreads();
    if (tid < 64) atomicAdd(&g_stats[b*64 + tid], sred[tid]);
}

// ---------------------------------------------------------------- GN + ReLU + NHWC->NCHW (smem transpose)
__global__ void norm_kernel(float* __restrict__ out,
                            const float* __restrict__ gamma,
                            const float* __restrict__ beta) {
    __shared__ float tile[32][33];
    const int m0 = blockIdx.x * 32;         // 576 tiles
    const int o0 = blockIdx.y * 32;         // 8 tiles
    const int tid = threadIdx.x;            // 256
    const int lane = tid & 31, row = tid >> 5;
    const int b = m0 / HW;                  // HW % 32 == 0

    // per-lane GN params for o = o0 + lane
    const int o = o0 + lane;
    const int g = o >> 3;
    float s  = g_stats[(b*NGRP + g)*2 + 0];
    float s2 = g_stats[(b*NGRP + g)*2 + 1];
    float mu  = s  * (1.f / (float)GELEMS);
    float var = s2 * (1.f / (float)GELEMS) - mu*mu;
    float scale = rsqrtf(var + 1e-5f) * gamma[o];
    float shift = beta[o] - mu * scale;

#pragma unroll
    for (int r = 0; r < 4; r++) {
        int ml = r*8 + row;
        float v = g_O[(size_t)(m0 + ml)*COUT + o];
        tile[ml][lane] = fmaxf(fmaf(v, scale, shift), 0.f);
    }
    __syncthreads();
#pragma unroll
    for (int r = 0; r < 4; r++) {
        int ol = r*8 + row;
        int m = m0 + lane;
        out[(size_t)(b*COUT + o0 + ol)*HW + (m - b*HW)] = tile[lane][ol];
    }
}

// ---------------------------------------------------------------- launch
extern "C" void kernel_launch(void* const* d_in, const int* in_sizes, int n_in,
                              void* d_out, int out_size) {
    const float* x     = (const float*)d_in[0];
    const float* off_w = (const float*)d_in[1];
    const float* off_b = (const float*)d_in[2];
    const float* cw    = (const float*)d_in[3];
    const float* gamma = (const float*)d_in[4];
    const float* beta  = (const float*)d_in[5];
    float* out = (float*)d_out;

    cudaFuncSetAttribute(gemm_kernel,
                         cudaFuncAttributeMaxDynamicSharedMemorySize, SMEM_BYTES);

    zero_stats_kernel<<<1, 128>>>();
    offset_conv_kernel<<<dim3(WW/32, HH/4, BB), dim3(32, 4)>>>(x, off_w, off_b);
    repack_w_kernel<<<(NK16*32*32*2 + 255)/256, 256>>>(cw);
    gather_kernel<<<dim3(HH, KK2, BB), WW>>>(x);
    gemm_kernel<<<MTOT/128, 512, SMEM_BYTES>>>();
    norm_kernel<<<dim3(MTOT/32, COUT/32), 256>>>(out, gamma, beta);
}